// round 2
// baseline (speedup 1.0000x reference)
#include <cuda_runtime.h>
#include <cuda_bf16.h>
#include <stdint.h>

// Problem shape (fixed by the dataset): BT=2048, HS=2048, HT=4096, V=32000
#define BT_MAX 2048
#define V_MAX  32000

// Scratch: device globals (no cudaMalloc allowed).
__device__ __nv_bfloat16 g_slog[(size_t)BT_MAX * V_MAX];  // student logits (bf16)
__device__ __nv_bfloat16 g_tlog[(size_t)BT_MAX * V_MAX];  // teacher logits (bf16)
__device__ float  g_lse_s[BT_MAX];
__device__ float  g_lse_t[BT_MAX];
__device__ float  g_inv_t[BT_MAX];   // 1 / sumexp_teacher
__device__ double g_acc[2];          // [0] = hard NLL sum, [1] = JSD sum

// ---------------------------------------------------------------------------
// exp(x) for small |x| via 6th-order Taylor (error < 3e-9 for |x|<=0.25).
// Falls back to __expf for |x| > 0.5 (never taken on this data distribution).
// ---------------------------------------------------------------------------
__device__ __forceinline__ float exp_poly(float x) {
    if (fabsf(x) > 0.5f) return __expf(x);
    float p = fmaf(x, 1.f/720.f, 1.f/120.f);
    p = fmaf(x, p, 1.f/24.f);
    p = fmaf(x, p, 1.f/6.f);
    p = fmaf(x, p, 0.5f);
    p = fmaf(x, p, 1.f);
    p = fmaf(x, p, 1.f);
    return p;
}

// Pointwise JSD: p*(a-m) + q*(b-m) with p=e^a, q=e^b, m=log((p+q)/2)
// == q * g(d), d = a-b, g(d) = e^d (d - c) - c, c = log((1+e^d)/2)
// Series: g(d) = d^2/4 + d^3/8 + d^4/32 + d^5/192 + O(d^6)
__device__ __forceinline__ float jsd_term(float s_logit, float t_logit,
                                          float dl, float inv_t) {
    float d = (s_logit - t_logit) - dl;          // a - b, small
    float q = exp_poly(t_logit) * inv_t;         // teacher probability
    float gg;
    if (fabsf(d) > 0.5f) {                       // exact fallback (never on this data)
        float ed = __expf(d);
        float c  = __logf(0.5f * (1.f + ed));
        gg = ed * (d - c) - c;
    } else {
        gg = d * d * (0.25f + d * (0.125f + d * (0.03125f + d * (1.f/192.f))));
    }
    return q * gg;
}

// ---------------------------------------------------------------------------
// GEMM: C[M,N](bf16) = A[M,K](f32) * W[N,K](f32)^T, via mma.sync bf16.
// Block tile 128x128x32, 256 threads = 8 warps (2 M x 4 N), warp tile 64x32.
// ---------------------------------------------------------------------------
__global__ void __launch_bounds__(256, 1)
gemm_logits_kernel(const float* __restrict__ A, const float* __restrict__ W,
                   int M, int N, int K, int which)
{
    __shared__ __nv_bfloat16 sA[128][34];   // pad to 34 to soften bank conflicts
    __shared__ __nv_bfloat16 sB[128][34];

    __nv_bfloat16* C = which ? g_tlog : g_slog;

    const int tid  = threadIdx.x;
    const int warp = tid >> 5, lane = tid & 31;
    const int wm = warp >> 2, wn = warp & 3;     // 2 x 4 warp grid
    const int g  = lane >> 2, t4 = lane & 3;     // mma group / quad id
    const int bm = blockIdx.y, bn = blockIdx.x;

    float acc[4][4][4];
#pragma unroll
    for (int i = 0; i < 4; i++)
#pragma unroll
        for (int j = 0; j < 4; j++)
#pragma unroll
            for (int c = 0; c < 4; c++) acc[i][j][c] = 0.f;

    const float* Ag = A + (size_t)bm * 128 * K;
    const float* Wg = W + (size_t)bn * 128 * K;

    for (int k0 = 0; k0 < K; k0 += 32) {
        // gmem loads (fp32), 4 float4 per thread per matrix
        float4 av[4], bv[4];
#pragma unroll
        for (int i = 0; i < 4; i++) {
            int f = tid + i * 256;               // float4 index in [0,1024)
            int r = f >> 3, kc = (f & 7) << 2;   // row, k-offset
            av[i] = *(const float4*)(Ag + (size_t)r * K + k0 + kc);
            bv[i] = *(const float4*)(Wg + (size_t)r * K + k0 + kc);
        }
        __syncthreads();                          // previous compute done
#pragma unroll
        for (int i = 0; i < 4; i++) {
            int f = tid + i * 256;
            int r = f >> 3, kc = (f & 7) << 2;
            *(__nv_bfloat162*)&sA[r][kc]     = __floats2bfloat162_rn(av[i].x, av[i].y);
            *(__nv_bfloat162*)&sA[r][kc + 2] = __floats2bfloat162_rn(av[i].z, av[i].w);
            *(__nv_bfloat162*)&sB[r][kc]     = __floats2bfloat162_rn(bv[i].x, bv[i].y);
            *(__nv_bfloat162*)&sB[r][kc + 2] = __floats2bfloat162_rn(bv[i].z, bv[i].w);
        }
        __syncthreads();

#pragma unroll
        for (int ks = 0; ks < 2; ks++) {
            const int kb = ks * 16;
            uint32_t afr[4][4];
            uint32_t bfr[4][2];
#pragma unroll
            for (int mt = 0; mt < 4; mt++) {
                int r0 = wm * 64 + mt * 16 + g;
                const uint32_t* p0 = (const uint32_t*)&sA[r0][kb + 2 * t4];
                const uint32_t* p1 = (const uint32_t*)&sA[r0 + 8][kb + 2 * t4];
                afr[mt][0] = p0[0];    // (g,   k 2t..2t+1)
                afr[mt][1] = p1[0];    // (g+8, k 2t..2t+1)
                afr[mt][2] = p0[4];    // (g,   k 2t+8..2t+9)
                afr[mt][3] = p1[4];    // (g+8, k 2t+8..2t+9)
            }
#pragma unroll
            for (int nt = 0; nt < 4; nt++) {
                int c = wn * 32 + nt * 8 + g;
                const uint32_t* q = (const uint32_t*)&sB[c][kb + 2 * t4];
                bfr[nt][0] = q[0];
                bfr[nt][1] = q[4];
            }
#pragma unroll
            for (int mt = 0; mt < 4; mt++)
#pragma unroll
                for (int nt = 0; nt < 4; nt++) {
                    asm volatile(
                        "mma.sync.aligned.m16n8k16.row.col.f32.bf16.bf16.f32 "
                        "{%0,%1,%2,%3}, {%4,%5,%6,%7}, {%8,%9}, {%0,%1,%2,%3};\n"
                        : "+f"(acc[mt][nt][0]), "+f"(acc[mt][nt][1]),
                          "+f"(acc[mt][nt][2]), "+f"(acc[mt][nt][3])
                        : "r"(afr[mt][0]), "r"(afr[mt][1]),
                          "r"(afr[mt][2]), "r"(afr[mt][3]),
                          "r"(bfr[nt][0]), "r"(bfr[nt][1]));
                }
        }
    }

    // Epilogue: write bf16 logits.
#pragma unroll
    for (int mt = 0; mt < 4; mt++) {
        int row = bm * 128 + wm * 64 + mt * 16 + g;
#pragma unroll
        for (int nt = 0; nt < 4; nt++) {
            int col = bn * 128 + wn * 32 + nt * 8 + 2 * t4;
            *(__nv_bfloat162*)(C + (size_t)row * N + col) =
                __floats2bfloat162_rn(acc[mt][nt][0], acc[mt][nt][1]);
            *(__nv_bfloat162*)(C + (size_t)(row + 8) * N + col) =
                __floats2bfloat162_rn(acc[mt][nt][2], acc[mt][nt][3]);
        }
    }
}

// ---------------------------------------------------------------------------
// Per-row: sumexp over V for both matrices -> lse_s, lse_t, 1/sum_t,
// plus hard-loss NLL (lse_s - logit[label]) accumulated into g_acc[0].
// ---------------------------------------------------------------------------
__global__ void __launch_bounds__(256)
rowstats_kernel(const int* __restrict__ labels, int V)
{
    const int r = blockIdx.x;
    const __nv_bfloat16* srow = g_slog + (size_t)r * V;
    const __nv_bfloat16* trow = g_tlog + (size_t)r * V;

    float ss = 0.f, st = 0.f;
    for (int i = threadIdx.x; i < V / 2; i += 256) {
        __nv_bfloat162 s2 = *(const __nv_bfloat162*)(srow + 2 * i);
        __nv_bfloat162 t2 = *(const __nv_bfloat162*)(trow + 2 * i);
        ss += exp_poly(__bfloat162float(s2.x)) + exp_poly(__bfloat162float(s2.y));
        st += exp_poly(__bfloat162float(t2.x)) + exp_poly(__bfloat162float(t2.y));
    }

    __shared__ float red[256];
    red[threadIdx.x] = ss;
    __syncthreads();
    for (int o = 128; o > 0; o >>= 1) {
        if (threadIdx.x < o) red[threadIdx.x] += red[threadIdx.x + o];
        __syncthreads();
    }
    float ssum = red[0];
    __syncthreads();
    red[threadIdx.x] = st;
    __syncthreads();
    for (int o = 128; o > 0; o >>= 1) {
        if (threadIdx.x < o) red[threadIdx.x] += red[threadIdx.x + o];
        __syncthreads();
    }
    float tsum = red[0];

    if (threadIdx.x == 0) {
        float ls = logf(ssum);
        float lt = logf(tsum);
        g_lse_s[r] = ls;
        g_lse_t[r] = lt;
        g_inv_t[r] = 1.0f / tsum;
        int lab = labels[r];
        if (lab != -100 && lab >= 0 && lab < V) {
            float nll = ls - __bfloat162float(srow[lab]);
            atomicAdd(&g_acc[0], (double)nll);
        }
    }
}

// ---------------------------------------------------------------------------
// JSD pass: sum q*g(d) over all (row, v), accumulate into g_acc[1].
// ---------------------------------------------------------------------------
__global__ void __launch_bounds__(256)
jsd_kernel(int V)
{
    const int r = blockIdx.y;
    const float ls    = g_lse_s[r];
    const float lt    = g_lse_t[r];
    const float inv_t = g_inv_t[r];
    const float dl    = ls - lt;

    const __nv_bfloat16* srow = g_slog + (size_t)r * V;
    const __nv_bfloat16* trow = g_tlog + (size_t)r * V;

    const int i0 = (blockIdx.x * 256 + threadIdx.x) * 8;
    float local = 0.f;
    if (i0 + 8 <= V) {
        uint4 sv = *(const uint4*)(srow + i0);
        uint4 tv = *(const uint4*)(trow + i0);
        const __nv_bfloat162* sp = (const __nv_bfloat162*)&sv;
        const __nv_bfloat162* tp = (const __nv_bfloat162*)&tv;
#pragma unroll
        for (int j = 0; j < 4; j++) {
            local += jsd_term(__bfloat162float(sp[j].x), __bfloat162float(tp[j].x), dl, inv_t);
            local += jsd_term(__bfloat162float(sp[j].y), __bfloat162float(tp[j].y), dl, inv_t);
        }
    }

    __shared__ float red[256];
    red[threadIdx.x] = local;
    __syncthreads();
    for (int o = 128; o > 0; o >>= 1) {
        if (threadIdx.x < o) red[threadIdx.x] += red[threadIdx.x + o];
        __syncthreads();
    }
    if (threadIdx.x == 0) atomicAdd(&g_acc[1], (double)red[0]);
}

__global__ void zero_kernel() {
    if (threadIdx.x == 0) { g_acc[0] = 0.0; g_acc[1] = 0.0; }
}

__global__ void finalize_kernel(float* out, int BT) {
    if (threadIdx.x == 0) {
        double hard = g_acc[0] / (double)BT;               // sum NLL / BT
        double soft = 0.5 * (g_acc[1] / (double)BT);       // 0.5*(s_kl + t_kl)
        out[0] = (float)(0.5 * hard + 0.5 * soft);         // W_HARD, W_SOFT
    }
}

// ---------------------------------------------------------------------------
extern "C" void kernel_launch(void* const* d_in, const int* in_sizes, int n_in,
                              void* d_out, int out_size)
{
    const float* s_in   = (const float*)d_in[0];
    const float* s_w    = (const float*)d_in[1];
    const float* t_in   = (const float*)d_in[2];
    const float* t_w    = (const float*)d_in[3];
    const int*   labels = (const int*)d_in[4];

    const int BT = in_sizes[4];
    const int HS = in_sizes[0] / BT;
    const int HT = in_sizes[2] / BT;
    const int V  = in_sizes[1] / HS;

    zero_kernel<<<1, 32>>>();

    dim3 block(256);
    dim3 grid_g(V / 128, BT / 128);
    gemm_logits_kernel<<<grid_g, block>>>(s_in, s_w, BT, V, HS, 0);
    gemm_logits_kernel<<<grid_g, block>>>(t_in, t_w, BT, V, HT, 1);

    rowstats_kernel<<<BT, 256>>>(labels, V);

    dim3 grid_j((V + 2047) / 2048, BT);
    jsd_kernel<<<grid_j, 256>>>(V);

    finalize_kernel<<<1, 32>>>((float*)d_out, BT);
}

// round 4
// speedup vs baseline: 3.0993x; 3.0993x over previous
#include <cuda_runtime.h>
#include <cuda_bf16.h>
#include <stdint.h>

// Fixed problem shape: BT=2048, HS=2048, HT=4096, V=32000
#define BTOK 2048
#define VOC  32000
#define HSK  2048
#define HTK  4096

// ---------------------------------------------------------------------------
// Device-global scratch (no cudaMalloc allowed).
// ---------------------------------------------------------------------------
__device__ __nv_bfloat16 g_slog[(size_t)BTOK * VOC];
__device__ __nv_bfloat16 g_tlog[(size_t)BTOK * VOC];
__device__ __nv_bfloat16 g_sa[(size_t)BTOK * HSK];
__device__ __nv_bfloat16 g_sw[(size_t)VOC * HSK];
__device__ __nv_bfloat16 g_ta[(size_t)BTOK * HTK];
__device__ __nv_bfloat16 g_tw[(size_t)VOC * HTK];
__device__ float  g_lse_s[BTOK];
__device__ float  g_lse_t[BTOK];
__device__ float  g_inv_t[BTOK];
__device__ double g_acc[2];          // [0]=hard NLL sum, [1]=JSD sum

// ---------------------------------------------------------------------------
// PTX helpers
// ---------------------------------------------------------------------------
__device__ __forceinline__ uint32_t smem_u32(const void* p) {
    uint32_t a;
    asm("{ .reg .u64 t; cvta.to.shared.u64 t, %1; cvt.u32.u64 %0, t; }" : "=r"(a) : "l"(p));
    return a;
}
__device__ __forceinline__ void cp_async16(uint32_t saddr, const void* gaddr) {
    asm volatile("cp.async.cg.shared.global [%0], [%1], 16;\n" :: "r"(saddr), "l"(gaddr));
}
__device__ __forceinline__ void cpasync_commit() {
    asm volatile("cp.async.commit_group;\n" ::: "memory");
}
#define LDSM_X4(r0, r1, r2, r3, addr) \
    asm volatile("ldmatrix.sync.aligned.m8n8.x4.shared.b16 {%0,%1,%2,%3}, [%4];" \
                 : "=r"(r0), "=r"(r1), "=r"(r2), "=r"(r3) : "r"(addr))

// ---------------------------------------------------------------------------
// Math helpers
// ---------------------------------------------------------------------------
__device__ __forceinline__ float exp_poly(float x) {
    if (fabsf(x) > 0.5f) return __expf(x);
    float p = fmaf(x, 1.f/720.f, 1.f/120.f);
    p = fmaf(x, p, 1.f/24.f);
    p = fmaf(x, p, 1.f/6.f);
    p = fmaf(x, p, 0.5f);
    p = fmaf(x, p, 1.f);
    p = fmaf(x, p, 1.f);
    return p;
}
__device__ __forceinline__ float jsd_term(float s_logit, float t_logit,
                                          float dl, float inv_t) {
    float d = (s_logit - t_logit) - dl;
    float q = exp_poly(t_logit) * inv_t;
    float gg;
    if (fabsf(d) > 0.5f) {
        float ed = __expf(d);
        float c  = __logf(0.5f * (1.f + ed));
        gg = ed * (d - c) - c;
    } else {
        gg = d * d * (0.25f + d * (0.125f + d * (0.03125f + d * (1.f/192.f))));
    }
    return q * gg;
}

// ---------------------------------------------------------------------------
// fp32 -> bf16 conversion (which: 0=s_in,1=s_w,2=t_in,3=t_w)
// ---------------------------------------------------------------------------
__global__ void __launch_bounds__(256)
convert_kernel(const float* __restrict__ in, int n, int which)
{
    __nv_bfloat16* out = (which == 0) ? g_sa : (which == 1) ? g_sw
                       : (which == 2) ? g_ta : g_tw;
    int i = (blockIdx.x * 256 + threadIdx.x) * 4;
    if (i < n) {
        float4 v = *(const float4*)(in + i);
        *(__nv_bfloat162*)(out + i)     = __floats2bfloat162_rn(v.x, v.y);
        *(__nv_bfloat162*)(out + i + 2) = __floats2bfloat162_rn(v.z, v.w);
    }
}

// ---------------------------------------------------------------------------
// HMMA GEMM: C[bm*128.., bn*128..] (bf16) = A[M,K](bf16) @ W[N,K]^T (bf16)
// 256 threads = 8 warps (2M x 4N), warp tile 64x32, K-stage 64,
// 3-stage cp.async pipeline, SW128-swizzled smem, ldmatrix operand loads.
// blockIdx.x = M tile (fast), blockIdx.y = N tile. which: 0=student, 1=teacher
// ---------------------------------------------------------------------------
static constexpr int GEMM_SMEM = 3 * 32768 + 1024;   // 3 stages + align slack

__global__ void __launch_bounds__(256, 2)
gemm_hmma_kernel(int K, int V, int which)
{
    const __nv_bfloat16* __restrict__ A = which ? g_ta : g_sa;
    const __nv_bfloat16* __restrict__ W = which ? g_tw : g_sw;
    __nv_bfloat16* __restrict__ C = which ? g_tlog : g_slog;

    extern __shared__ char dynsmem[];
    const uint32_t sbase = (smem_u32(dynsmem) + 1023u) & ~1023u;

    const int tid = threadIdx.x;
    const int bm = blockIdx.x, bn = blockIdx.y;
    const int nc = K >> 6;                       // K / 64

    const int w  = tid >> 5, l = tid & 31;
    const int wm = w >> 2,  wn = w & 3;          // 2 x 4 warp grid
    const int lr = l & 7,   lm = l >> 3;         // ldmatrix: row-in-group, matrix idx
    const int g  = l >> 2,  t4 = l & 3;          // mma accumulator mapping

    float acc[4][4][4];
#pragma unroll
    for (int i = 0; i < 4; i++)
#pragma unroll
        for (int j = 0; j < 4; j++)
#pragma unroll
            for (int c = 0; c < 4; c++) acc[i][j][c] = 0.f;

    // Stage loader: A rows 0..127 (16KB) then B rows 0..127 (16KB), 128B rows,
    // SW128 swizzle (chunk' = chunk ^ (row&7)); 8 x 16B cp.async per thread.
    auto load_stage = [&](int slot, int chunk) {
        const int k0 = chunk << 6;
        const uint32_t sb = sbase + (uint32_t)slot * 32768u;
#pragma unroll
        for (int j = 0; j < 8; j++) {
            int i = tid + j * 256;               // 0..2047
            bool isA = (i < 1024);
            int ii = i & 1023;
            int r = ii >> 3, ck = ii & 7;
            const __nv_bfloat16* gp = isA
                ? (A + (size_t)(bm * 128 + r) * K + k0 + ck * 8)
                : (W + (size_t)(bn * 128 + r) * K + k0 + ck * 8);
            uint32_t so = (isA ? 0u : 16384u) + (uint32_t)(r * 128 + ((ck ^ (r & 7)) << 4));
            cp_async16(sb + so, gp);
        }
    };

    load_stage(0, 0); cpasync_commit();
    load_stage(1, 1); cpasync_commit();

    for (int c = 0; c < nc; c++) {
        if (c + 1 < nc) asm volatile("cp.async.wait_group 1;\n" ::: "memory");
        else            asm volatile("cp.async.wait_group 0;\n" ::: "memory");
        __syncthreads();

        if (c + 2 < nc) { load_stage((c + 2) % 3, c + 2); cpasync_commit(); }

        const uint32_t st = sbase + (uint32_t)(c % 3) * 32768u;

#pragma unroll
        for (int ks = 0; ks < 4; ks++) {
            // A fragments: 4 m-tiles of 16x16
            uint32_t af[4][4];
#pragma unroll
            for (int mt = 0; mt < 4; mt++) {
                int row = wm * 64 + mt * 16 + ((lm & 1) << 3) + lr;
                int ck  = ks * 2 + (lm >> 1);
                uint32_t ad = st + (uint32_t)(row * 128 + ((ck ^ (row & 7)) << 4));
                LDSM_X4(af[mt][0], af[mt][1], af[mt][2], af[mt][3], ad);
            }
            // B fragments: 2 n16 x k16 loads -> 4 n-tiles of 8
            uint32_t bf[2][4];
#pragma unroll
            for (int np = 0; np < 2; np++) {
                int row = wn * 32 + np * 16 + ((lm & 1) << 3) + lr;
                int ck  = ks * 2 + (lm >> 1);
                uint32_t ad = st + 16384u + (uint32_t)(row * 128 + ((ck ^ (row & 7)) << 4));
                LDSM_X4(bf[np][0], bf[np][1], bf[np][2], bf[np][3], ad);
            }
#pragma unroll
            for (int mt = 0; mt < 4; mt++)
#pragma unroll
                for (int nt = 0; nt < 4; nt++) {
                    uint32_t b0 = bf[nt >> 1][nt & 1];
                    uint32_t b1 = bf[nt >> 1][(nt & 1) + 2];
                    asm volatile(
                        "mma.sync.aligned.m16n8k16.row.col.f32.bf16.bf16.f32 "
                        "{%0,%1,%2,%3}, {%4,%5,%6,%7}, {%8,%9}, {%0,%1,%2,%3};\n"
                        : "+f"(acc[mt][nt][0]), "+f"(acc[mt][nt][1]),
                          "+f"(acc[mt][nt][2]), "+f"(acc[mt][nt][3])
                        : "r"(af[mt][0]), "r"(af[mt][1]),
                          "r"(af[mt][2]), "r"(af[mt][3]),
                          "r"(b0), "r"(b1));
                }
        }
    }

    // Epilogue: bf16 logits straight from registers.
#pragma unroll
    for (int mt = 0; mt < 4; mt++) {
        int row = bm * 128 + wm * 64 + mt * 16 + g;
#pragma unroll
        for (int nt = 0; nt < 4; nt++) {
            int col = bn * 128 + wn * 32 + nt * 8 + 2 * t4;
            *(__nv_bfloat162*)(C + (size_t)row * V + col) =
                __floats2bfloat162_rn(acc[mt][nt][0], acc[mt][nt][1]);
            *(__nv_bfloat162*)(C + (size_t)(row + 8) * V + col) =
                __floats2bfloat162_rn(acc[mt][nt][2], acc[mt][nt][3]);
        }
    }
}

// ---------------------------------------------------------------------------
// Per-row sumexp (student+teacher) + hard-loss NLL
// ---------------------------------------------------------------------------
__global__ void __launch_bounds__(256)
rowstats_kernel(const int* __restrict__ labels, int V)
{
    const int r = blockIdx.x;
    const __nv_bfloat16* srow = g_slog + (size_t)r * V;
    const __nv_bfloat16* trow = g_tlog + (size_t)r * V;

    float ss = 0.f, st = 0.f;
    for (int i = threadIdx.x; i < V / 2; i += 256) {
        __nv_bfloat162 s2 = *(const __nv_bfloat162*)(srow + 2 * i);
        __nv_bfloat162 t2 = *(const __nv_bfloat162*)(trow + 2 * i);
        ss += exp_poly(__bfloat162float(s2.x)) + exp_poly(__bfloat162float(s2.y));
        st += exp_poly(__bfloat162float(t2.x)) + exp_poly(__bfloat162float(t2.y));
    }

    __shared__ float red[256];
    red[threadIdx.x] = ss;
    __syncthreads();
    for (int o = 128; o > 0; o >>= 1) {
        if (threadIdx.x < o) red[threadIdx.x] += red[threadIdx.x + o];
        __syncthreads();
    }
    float ssum = red[0];
    __syncthreads();
    red[threadIdx.x] = st;
    __syncthreads();
    for (int o = 128; o > 0; o >>= 1) {
        if (threadIdx.x < o) red[threadIdx.x] += red[threadIdx.x + o];
        __syncthreads();
    }
    float tsum = red[0];

    if (threadIdx.x == 0) {
        float ls = logf(ssum);
        float lt = logf(tsum);
        g_lse_s[r] = ls;
        g_lse_t[r] = lt;
        g_inv_t[r] = 1.0f / tsum;
        int lab = labels[r];
        if (lab != -100 && lab >= 0 && lab < V) {
            float nll = ls - __bfloat162float(srow[lab]);
            atomicAdd(&g_acc[0], (double)nll);
        }
    }
}

// ---------------------------------------------------------------------------
// JSD pass
// ---------------------------------------------------------------------------
__global__ void __launch_bounds__(256)
jsd_kernel(int V)
{
    const int r = blockIdx.y;
    const float ls    = g_lse_s[r];
    const float lt    = g_lse_t[r];
    const float inv_t = g_inv_t[r];
    const float dl    = ls - lt;

    const __nv_bfloat16* srow = g_slog + (size_t)r * V;
    const __nv_bfloat16* trow = g_tlog + (size_t)r * V;

    const int i0 = (blockIdx.x * 256 + threadIdx.x) * 8;
    float local = 0.f;
    if (i0 + 8 <= V) {
        uint4 sv = *(const uint4*)(srow + i0);
        uint4 tv = *(const uint4*)(trow + i0);
        const __nv_bfloat162* sp = (const __nv_bfloat162*)&sv;
        const __nv_bfloat162* tp = (const __nv_bfloat162*)&tv;
#pragma unroll
        for (int j = 0; j < 4; j++) {
            local += jsd_term(__bfloat162float(sp[j].x), __bfloat162float(tp[j].x), dl, inv_t);
            local += jsd_term(__bfloat162float(sp[j].y), __bfloat162float(tp[j].y), dl, inv_t);
        }
    }

    __shared__ float red[256];
    red[threadIdx.x] = local;
    __syncthreads();
    for (int o = 128; o > 0; o >>= 1) {
        if (threadIdx.x < o) red[threadIdx.x] += red[threadIdx.x + o];
        __syncthreads();
    }
    if (threadIdx.x == 0) atomicAdd(&g_acc[1], (double)red[0]);
}

__global__ void zero_kernel() {
    if (threadIdx.x == 0) { g_acc[0] = 0.0; g_acc[1] = 0.0; }
}

__global__ void finalize_kernel(float* out, int BT) {
    if (threadIdx.x == 0) {
        double hard = g_acc[0] / (double)BT;
        double soft = 0.5 * (g_acc[1] / (double)BT);
        out[0] = (float)(0.5 * hard + 0.5 * soft);
    }
}

// ---------------------------------------------------------------------------
extern "C" void kernel_launch(void* const* d_in, const int* in_sizes, int n_in,
                              void* d_out, int out_size)
{
    const float* s_in   = (const float*)d_in[0];
    const float* s_w    = (const float*)d_in[1];
    const float* t_in   = (const float*)d_in[2];
    const float* t_w    = (const float*)d_in[3];
    const int*   labels = (const int*)d_in[4];

    const int BT = in_sizes[4];
    const int HS = in_sizes[0] / BT;
    const int HT = in_sizes[2] / BT;
    const int V  = in_sizes[1] / HS;

    cudaFuncSetAttribute(gemm_hmma_kernel,
                         cudaFuncAttributeMaxDynamicSharedMemorySize, GEMM_SMEM);

    zero_kernel<<<1, 32>>>();

    convert_kernel<<<(in_sizes[0] / 4 + 255) / 256, 256>>>(s_in, in_sizes[0], 0);
    convert_kernel<<<(in_sizes[1] / 4 + 255) / 256, 256>>>(s_w,  in_sizes[1], 1);
    convert_kernel<<<(in_sizes[2] / 4 + 255) / 256, 256>>>(t_in, in_sizes[2], 2);
    convert_kernel<<<(in_sizes[3] / 4 + 255) / 256, 256>>>(t_w,  in_sizes[3], 3);

    dim3 gg(BT / 128, V / 128);
    gemm_hmma_kernel<<<gg, 256, GEMM_SMEM>>>(HS, V, 0);
    gemm_hmma_kernel<<<gg, 256, GEMM_SMEM>>>(HT, V, 1);

    rowstats_kernel<<<BT, 256>>>(labels, V);

    dim3 gj((V + 2047) / 2048, BT);
    jsd_kernel<<<gj, 256>>>(V);

    finalize_kernel<<<1, 32>>>((float*)d_out, BT);
}